// round 16
// baseline (speedup 1.0000x reference)
#include <cuda_runtime.h>
#include <cuda_bf16.h>
#include <math.h>

constexpr int Bc = 8;
constexpr int Cc = 64;
constexpr int Nc = 4096;
constexpr int Kc = 20;
constexpr int KR = 24;
constexpr int Oc = 64;
constexpr float BN_EPS = 1e-5f;
constexpr float NEG_SLOPE = 0.2f;
constexpr float FLT_BIG = 3.4e38f;

constexpr int ASTR = 200;   // A tile row stride (bf16), 192 + 8 pad
constexpr int BSTR = 136;   // B tile row stride (bf16), 128 + 8 pad
constexpr int NSLOT = 512;  // top-k slots (4 colbands x 128 queries)

typedef unsigned long long u64;
typedef unsigned int u32;

// -------------------- device scratch --------------------
__device__ float  g_xx[Bc * Nc];
__device__ int    g_idx[Bc * Nc * Kc];
__device__ int    g_cand[Bc * Nc * KR];
__device__ float  g_P[Bc * Nc * Oc];
__device__ float  g_Q[Bc * Nc * Oc];
__device__ float  g_mx[Bc * Nc * Oc];
__device__ float  g_mn[Bc * Nc * Oc];
__device__ double g_sum[Oc];
__device__ double g_sumsq[Oc];
__device__ float  g_scale[Oc];
__device__ float  g_shift[Oc];
__device__ float  g_W1t[Cc * Oc];
__device__ float  g_Wdt[Cc * Oc];
__device__ __nv_bfloat16 g_ae[(size_t)Bc * Nc * 192];  // [row][h(64) l(64) h(64)]
__device__ float  g_xt[(size_t)Bc * Nc * Cc];          // transposed x (rescue)

// -------------------- helpers --------------------
__device__ __forceinline__ u32 ordf(float f) {
    u32 u = __float_as_uint(f);
    return (u & 0x80000000u) ? ~u : (u | 0x80000000u);
}
__device__ __forceinline__ float inv_ordf(u32 v) {
    u32 u = (v & 0x80000000u) ? (v & 0x7FFFFFFFu) : ~v;
    return __uint_as_float(u);
}
constexpr u64 KEY_MAX = 0xFFFFFFFFFFFFFFFFull;

__device__ __forceinline__ u32 smem_u32(const void* p) {
    u32 a;
    asm("{ .reg .u64 t; cvta.to.shared.u64 t, %1; cvt.u32.u64 %0, t; }"
        : "=r"(a) : "l"(p));
    return a;
}
__device__ __forceinline__ void ldsm4(u32* r, u32 a) {
    asm volatile("ldmatrix.sync.aligned.m8n8.x4.shared.b16 {%0,%1,%2,%3}, [%4];"
        : "=r"(r[0]), "=r"(r[1]), "=r"(r[2]), "=r"(r[3]) : "r"(a));
}
__device__ __forceinline__ void ldsm2(u32* r, u32 a) {
    asm volatile("ldmatrix.sync.aligned.m8n8.x2.shared.b16 {%0,%1}, [%2];"
        : "=r"(r[0]), "=r"(r[1]) : "r"(a));
}
__device__ __forceinline__ void mma_bf16(float* d, const u32* a, const u32* b) {
    asm volatile("mma.sync.aligned.m16n8k16.row.col.f32.bf16.bf16.f32 "
        "{%0,%1,%2,%3},{%4,%5,%6,%7},{%8,%9},{%0,%1,%2,%3};"
        : "+f"(d[0]), "+f"(d[1]), "+f"(d[2]), "+f"(d[3])
        : "r"(a[0]), "r"(a[1]), "r"(a[2]), "r"(a[3]), "r"(b[0]), "r"(b[1]));
}

// -------------------- kernel: squared norms --------------------
__global__ void k_xx(const float* __restrict__ x) {
    int t = blockIdx.x * blockDim.x + threadIdx.x;
    int b = t >> 12;
    int n = t & (Nc - 1);
    const float* xb = x + (size_t)b * Cc * Nc + n;
    float s = 0.f;
#pragma unroll
    for (int c = 0; c < Cc; ++c) {
        float v = xb[c * Nc];
        s = fmaf(v, v, s);
    }
    g_xx[t] = s;
}

// -------------------- kernel: prep W + zero stats --------------------
__global__ void k_prep(const float* __restrict__ W) {
    int t = blockIdx.x * blockDim.x + threadIdx.x;
    if (t < Cc * Oc) {
        int c = t & 63;
        int o = t >> 6;
        float w1 = W[o * (2 * Cc) + c];
        float w2 = W[o * (2 * Cc) + Cc + c];
        g_W1t[c * Oc + o] = w1;
        g_Wdt[c * Oc + o] = w2 - w1;
    }
    if (blockIdx.x == 0 && t < Oc) {
        g_sum[t] = 0.0;
        g_sumsq[t] = 0.0;
    }
}

// -------------------- kernel: P/Q projections --------------------
__global__ void __launch_bounds__(256) k_pq(const float* __restrict__ x) {
    int b  = blockIdx.y;
    int n0 = blockIdx.x * 32;
    int o  = threadIdx.x & 63;
    int gg = threadIdx.x >> 6;
    __shared__ float xs[Cc][36];
    for (int t = threadIdx.x; t < Cc * 32; t += 256) {
        int nn = t & 31;
        int c  = t >> 5;
        xs[c][nn] = x[(size_t)b * Cc * Nc + c * Nc + n0 + nn];
    }
    __syncthreads();
    float ap[8], aq[8];
#pragma unroll
    for (int r = 0; r < 8; ++r) { ap[r] = 0.f; aq[r] = 0.f; }
    const int nbase = gg * 8;
#pragma unroll 8
    for (int c = 0; c < Cc; ++c) {
        float w1 = __ldg(&g_W1t[c * Oc + o]);
        float wd = __ldg(&g_Wdt[c * Oc + o]);
        float4 v0 = *(const float4*)&xs[c][nbase];
        float4 v1 = *(const float4*)&xs[c][nbase + 4];
        ap[0] = fmaf(w1, v0.x, ap[0]); aq[0] = fmaf(wd, v0.x, aq[0]);
        ap[1] = fmaf(w1, v0.y, ap[1]); aq[1] = fmaf(wd, v0.y, aq[1]);
        ap[2] = fmaf(w1, v0.z, ap[2]); aq[2] = fmaf(wd, v0.z, aq[2]);
        ap[3] = fmaf(w1, v0.w, ap[3]); aq[3] = fmaf(wd, v0.w, aq[3]);
        ap[4] = fmaf(w1, v1.x, ap[4]); aq[4] = fmaf(wd, v1.x, aq[4]);
        ap[5] = fmaf(w1, v1.y, ap[5]); aq[5] = fmaf(wd, v1.y, aq[5]);
        ap[6] = fmaf(w1, v1.z, ap[6]); aq[6] = fmaf(wd, v1.z, aq[6]);
        ap[7] = fmaf(w1, v1.w, ap[7]); aq[7] = fmaf(wd, v1.w, aq[7]);
    }
    int row0 = b * Nc + n0 + nbase;
#pragma unroll
    for (int r = 0; r < 8; ++r) {
        g_P[(size_t)(row0 + r) * Oc + o] = ap[r];
        g_Q[(size_t)(row0 + r) * Oc + o] = aq[r];
    }
}

// -------------------- kernel: build split rows [h,l,h] + transposed fp32 -----
// NOTE: staging tile padded to 68 floats/row (272B = 17*16) so float4 reads
// are 16B-aligned on every row (65-pad caused the R15 misaligned-address).
__global__ void __launch_bounds__(256) k_split(const float* __restrict__ x) {
    int b = blockIdx.y, n0 = blockIdx.x * 64;
    __shared__ float sh[64][68];
    for (int idx = threadIdx.x; idx < 4096; idx += 256) {
        int c = idx >> 6, nn = idx & 63;
        sh[nn][c] = x[((size_t)b * Cc + c) * Nc + n0 + nn];
    }
    __syncthreads();
    int nn = threadIdx.x >> 2, part = threadIdx.x & 3, cs = part * 16;
    size_t row = (size_t)(b << 12) + n0 + nn;
    __nv_bfloat16* ar = g_ae + row * 192;
    float* xr = g_xt + row * 64;
    __nv_bfloat16 hb[16], lb[16];
#pragma unroll
    for (int c4 = 0; c4 < 4; ++c4) {
        float4 v = *(const float4*)&sh[nn][cs + c4 * 4];
        *(float4*)&xr[cs + c4 * 4] = v;
        float vv[4] = {v.x, v.y, v.z, v.w};
#pragma unroll
        for (int k = 0; k < 4; ++k) {
            __nv_bfloat16 h = __float2bfloat16(vv[k]);
            hb[c4 * 4 + k] = h;
            lb[c4 * 4 + k] = __float2bfloat16(vv[k] - __bfloat162float(h));
        }
    }
    const uint4* hv = (const uint4*)hb;
    const uint4* lv = (const uint4*)lb;
    *(uint4*)&ar[cs]       = hv[0]; *(uint4*)&ar[cs + 8]       = hv[1];
    *(uint4*)&ar[64 + cs]  = lv[0]; *(uint4*)&ar[64 + cs + 8]  = lv[1];
    *(uint4*)&ar[128 + cs] = hv[0]; *(uint4*)&ar[128 + cs + 8] = hv[1];
}

// -------------------- insert (rare path) --------------------
__device__ __forceinline__ void try_ins(u64* keys, float* wf, int slot, float d, int j) {
    u64 key = ((u64)ordf(d) << 32) | (u32)j;
    if (key < keys[(KR - 1) * NSLOT + slot]) {
        int p = KR - 1;
        while (p > 0) {
            u64 v = keys[(p - 1) * NSLOT + slot];
            if (v < key) break;
            keys[p * NSLOT + slot] = v;
            --p;
        }
        keys[p * NSLOT + slot] = key;
        u32 hi = (u32)(keys[(KR - 1) * NSLOT + slot] >> 32);
        wf[slot] = (hi == 0xFFFFFFFFu) ? FLT_BIG : inv_ordf(hi);
    }
}

// -------------------- kernel: HMMA KNN v3 — 16 warps, register scan ----------
// grid (32, 8), 512 threads, smem ~187KB. Block tile 128q x 128j; warp
// (rb=w>>2, cb=w&3) owns 32q x 32j via the R13-proven m16n8k16 micro-kernel
// (16 ksteps = bf16 h/l split product). Distances finish IN REGISTERS
// (dacc overwritten in place); qualify vs shared wf[slot], warp ballot,
// rare inserts serialized only within each 4-lane quad. No Ds round-trip.
__global__ void __launch_bounds__(512) k_tc() {
    extern __shared__ char smc[];
    u64*   keys = (u64*)smc;                       // [KR][NSLOT]
    char*  smA  = smc + KR * NSLOT * 8;            // 128 x ASTR bf16
    char*  smB  = smA + 128 * ASTR * 2;            // 128 x BSTR bf16
    float* wf   = (float*)(smB + 128 * BSTR * 2);  // [NSLOT]
    float* sxxi = wf + NSLOT;                      // [128]
    float* sxxj = sxxi + 128;                      // [128]

    const int tid  = threadIdx.x;
    const int lane = tid & 31;
    const int w    = tid >> 5;
    const int rb   = w >> 2;                       // row band (0..3)
    const int cb   = w & 3;                        // col band (0..3)
    const int b    = blockIdx.y;
    const int i0   = blockIdx.x * 128;
    const size_t rbase = (size_t)(b << 12) + i0;

    // load A tile (once): 128 rows x 24 16B-chunks
#pragma unroll
    for (int cc = 0; cc < 6; ++cc) {
        int cid = tid + 512 * cc;
        int row = cid / 24, kc = cid % 24;
        uint4 v = *(const uint4*)&g_ae[(rbase + row) * 192 + kc * 8];
        *(uint4*)(smA + row * (ASTR * 2) + kc * 16) = v;
    }
    if (tid < 128) sxxi[tid] = g_xx[rbase + tid];
    wf[tid] = FLT_BIG;
#pragma unroll
    for (int kk = 0; kk < KR; ++kk) keys[kk * NSLOT + tid] = KEY_MAX;
    __syncthreads();

    const u32 smA0 = smem_u32(smA);
    const u32 smB0 = smem_u32(smB);
    const u32 aBase = smA0 + ((rb * 32 + (lane & 15)) * ASTR + (lane >> 4) * 8) * 2;
    const u32 bBase = smB0 + ((cb * 32 + (lane & 7)) * BSTR + ((lane >> 3) & 1) * 8) * 2;

    for (int t = 0; t < 32; ++t) {
        const int j0 = t * 128;
        // load B tile: 128 rows x 16 16B-chunks
#pragma unroll
        for (int cc = 0; cc < 4; ++cc) {
            int cid = tid + 512 * cc;
            int row = cid >> 4, kc = cid & 15;
            uint4 v = *(const uint4*)&g_ae[((size_t)(b << 12) + j0 + row) * 192 + kc * 8];
            *(uint4*)(smB + row * (BSTR * 2) + kc * 16) = v;
        }
        if (tid < 128) sxxj[tid] = g_xx[(b << 12) + j0 + tid];
        __syncthreads();

        // ---- MMA: 16 ksteps (h/l split), 8 mma each (R13-proven layout) ----
        float dacc[2][4][4];
#pragma unroll
        for (int mb = 0; mb < 2; ++mb)
#pragma unroll
            for (int nb = 0; nb < 4; ++nb)
#pragma unroll
                for (int s = 0; s < 4; ++s) dacc[mb][nb][s] = 0.f;

#pragma unroll
        for (int kk = 0; kk < 16; ++kk) {
            const int a_k = (kk < 8) ? kk * 16 : 64 + (kk - 8) * 16;
            const int b_k = (kk & 7) * 16;
            u32 af[2][4], bf[4][2];
            ldsm4(af[0], aBase + a_k * 2);
            ldsm4(af[1], aBase + (16 * ASTR + a_k) * 2);
#pragma unroll
            for (int nb = 0; nb < 4; ++nb)
                ldsm2(bf[nb], bBase + (nb * 8 * BSTR + b_k) * 2);
#pragma unroll
            for (int mb = 0; mb < 2; ++mb)
#pragma unroll
                for (int nb = 0; nb < 4; ++nb)
                    mma_bf16(dacc[mb][nb], af[mb], bf[nb]);
        }

        // ---- epilogue in registers: d = xxi + xxj - 2*dot (in place) ----
        bool anyq = false;
#pragma unroll
        for (int mb = 0; mb < 2; ++mb) {
            int rl = rb * 32 + mb * 16 + (lane >> 2);
            float xi0 = sxxi[rl], xi8 = sxxi[rl + 8];
            float w0 = wf[cb * 128 + rl], w1 = wf[cb * 128 + rl + 8];
#pragma unroll
            for (int nb = 0; nb < 4; ++nb) {
                int c = cb * 32 + nb * 8 + (lane & 3) * 2;
                float xj0 = sxxj[c], xj1 = sxxj[c + 1];
                float d0 = fmaf(-2.f, dacc[mb][nb][0], xi0 + xj0);
                float d1 = fmaf(-2.f, dacc[mb][nb][1], xi0 + xj1);
                float d2 = fmaf(-2.f, dacc[mb][nb][2], xi8 + xj0);
                float d3 = fmaf(-2.f, dacc[mb][nb][3], xi8 + xj1);
                dacc[mb][nb][0] = d0; dacc[mb][nb][1] = d1;
                dacc[mb][nb][2] = d2; dacc[mb][nb][3] = d3;
                anyq = anyq | (d0 < w0) | (d1 < w0) | (d2 < w1) | (d3 < w1);
            }
        }

        // ---- rare path: quad-serialized inserts into private slots ----
        if (__ballot_sync(0xFFFFFFFFu, anyq)) {
#pragma unroll 1
            for (int r4 = 0; r4 < 4; ++r4) {
                if ((lane & 3) == r4 && anyq) {
#pragma unroll
                    for (int mb = 0; mb < 2; ++mb)
#pragma unroll
                        for (int nb = 0; nb < 4; ++nb)
#pragma unroll
                            for (int s = 0; s < 4; ++s) {
                                float d = dacc[mb][nb][s];
                                int rl = rb * 32 + mb * 16 + (lane >> 2) + ((s & 2) ? 8 : 0);
                                int slot = cb * 128 + rl;
                                if (d < wf[slot]) {
                                    int j = j0 + cb * 32 + nb * 8 + (lane & 3) * 2 + (s & 1);
                                    try_ins(keys, wf, slot, d, j);
                                }
                            }
                }
                __syncwarp();
            }
        }
        __syncthreads();   // all warps done before smB overwrite
    }

    // merge the 4 colband lists per query -> top-KR candidates
    if (tid < 128) {
        u64 tk[KR];
#pragma unroll
        for (int kk = 0; kk < KR; ++kk) tk[kk] = KEY_MAX;
        for (int s = 0; s < 4; ++s) {
#pragma unroll 1
            for (int kk = 0; kk < KR; ++kk) {
                u64 key = keys[kk * NSLOT + s * 128 + tid];
                if (!(key < tk[KR - 1])) break;
                int p = KR - 1;
                while (p > 0 && tk[p - 1] > key) {
                    tk[p] = tk[p - 1];
                    --p;
                }
                tk[p] = key;
            }
        }
        int* op = &g_cand[(rbase + tid) * KR];
#pragma unroll
        for (int kk = 0; kk < KR; ++kk) op[kk] = (int)(u32)(tk[kk] & 0xFFFFFFFFull);
    }
}

// -------------------- kernel: exact rescue (24 -> exact top-20) --------------
__global__ void __launch_bounds__(256) k_rescue() {
    int tid = threadIdx.x, lane = tid & 31;
    int q = blockIdx.x * 8 + (tid >> 5);
    int b = q >> 12;
    u64 key = KEY_MAX;
    if (lane < KR) {
        int j = g_cand[(size_t)q * KR + lane];
        const float* xi = &g_xt[(size_t)q * 64];
        const float* xj = &g_xt[((size_t)(b << 12) + j) * 64];
        float dot = 0.f;
#pragma unroll
        for (int c = 0; c < 64; c += 4) {
            float4 a = *(const float4*)&xi[c];
            float4 bb = *(const float4*)&xj[c];
            dot = fmaf(a.x, bb.x, dot); dot = fmaf(a.y, bb.y, dot);
            dot = fmaf(a.z, bb.z, dot); dot = fmaf(a.w, bb.w, dot);
        }
        float d = g_xx[q] + g_xx[(b << 12) + j] - 2.f * dot;
        key = ((u64)ordf(d) << 32) | (u32)j;
    }
#pragma unroll
    for (int k2 = 2; k2 <= 32; k2 <<= 1) {
#pragma unroll
        for (int jj = k2 >> 1; jj > 0; jj >>= 1) {
            u64 o = __shfl_xor_sync(0xFFFFFFFFu, key, jj);
            bool tmax = ((lane & jj) != 0) == ((lane & k2) == 0);
            key = tmax ? (key > o ? key : o) : (key < o ? key : o);
        }
    }
    if (lane < Kc)
        g_idx[(size_t)q * Kc + lane] = (int)(u32)(key & 0xFFFFFFFFull);
}

// -------------------- kernel: gather + max/min + BN stats --------------------
__global__ void __launch_bounds__(256) k_edge() {
    int o  = threadIdx.x & 63;
    int gg = threadIdx.x >> 6;
    float s1 = 0.f, s2v = 0.f;
    for (int row = blockIdx.x * 4 + gg; row < Bc * Nc; row += gridDim.x * 4) {
        int b  = row >> 12;
        int nb = b << 12;
        float qv = g_Q[(size_t)row * Oc + o];
        const int* ip = &g_idx[(size_t)row * Kc];
        float mx = -FLT_BIG, mn = FLT_BIG;
#pragma unroll
        for (int kk = 0; kk < Kc; ++kk) {
            int j = __ldg(&ip[kk]);
            float h = g_P[(size_t)(nb + j) * Oc + o] + qv;
            mx = fmaxf(mx, h);
            mn = fminf(mn, h);
            s1 += h;
            s2v = fmaf(h, h, s2v);
        }
        g_mx[(size_t)row * Oc + o] = mx;
        g_mn[(size_t)row * Oc + o] = mn;
    }
    __shared__ float sa[4][64], sb[4][64];
    sa[gg][o] = s1;
    sb[gg][o] = s2v;
    __syncthreads();
    if (gg == 0) {
        float t1 = sa[0][o] + sa[1][o] + sa[2][o] + sa[3][o];
        float t2 = sb[0][o] + sb[1][o] + sb[2][o] + sb[3][o];
        atomicAdd(&g_sum[o], (double)t1);
        atomicAdd(&g_sumsq[o], (double)t2);
    }
}

// -------------------- kernel: finalize BN affine --------------------
__global__ void k_fin(const float* __restrict__ gamma, const float* __restrict__ beta) {
    int o = threadIdx.x;
    const double cnt = (double)Bc * Nc * Kc;
    double mean = g_sum[o] / cnt;
    double var  = g_sumsq[o] / cnt - mean * mean;
    float a = gamma[o] * rsqrtf((float)var + BN_EPS);
    g_scale[o] = a;
    g_shift[o] = beta[o] - (float)mean * a;
}

// -------------------- kernel: affine + leaky + transpose --------------------
__global__ void __launch_bounds__(256) k_out(float* __restrict__ out) {
    int b  = blockIdx.y;
    int n0 = blockIdx.x * 64;
    __shared__ float sh[64][65];
    for (int t = threadIdx.x; t < 4096; t += 256) {
        int o  = t & 63;
        int nn = t >> 6;
        int row = b * Nc + n0 + nn;
        float a = g_scale[o];
        float m = (a >= 0.f) ? g_mx[(size_t)row * Oc + o] : g_mn[(size_t)row * Oc + o];
        float v = fmaf(a, m, g_shift[o]);
        v = (v >= 0.f) ? v : NEG_SLOPE * v;
        sh[o][nn] = v;
    }
    __syncthreads();
    for (int t = threadIdx.x; t < 4096; t += 256) {
        int nn = t & 63;
        int o  = t >> 6;
        out[((size_t)(b * Oc + o)) * Nc + n0 + nn] = sh[o][nn];
    }
}

// -------------------- launch --------------------
extern "C" void kernel_launch(void* const* d_in, const int* in_sizes, int n_in,
                              void* d_out, int out_size) {
    const float* x     = (const float*)d_in[0];
    const float* W     = (const float*)d_in[1];
    const float* gamma = (const float*)d_in[2];
    const float* beta  = (const float*)d_in[3];
    float* out = (float*)d_out;

    // keys + A tile + B tile + wf + sxxi + sxxj
    constexpr size_t TC_SMEM = (size_t)KR * NSLOT * 8
        + 128 * ASTR * 2 + 128 * BSTR * 2 + NSLOT * 4 + 128 * 4 + 128 * 4;

    static bool attr_set = false;
    if (!attr_set) {
        cudaFuncSetAttribute(k_tc, cudaFuncAttributeMaxDynamicSharedMemorySize,
                             (int)TC_SMEM);
        attr_set = true;
    }

    k_xx<<<(Bc * Nc) / 256, 256>>>(x);
    k_prep<<<16, 256>>>(W);
    k_pq<<<dim3(Nc / 32, Bc), 256>>>(x);
    k_split<<<dim3(Nc / 64, Bc), 256>>>(x);
    k_tc<<<dim3(Nc / 128, Bc), 512, TC_SMEM>>>();
    k_rescue<<<(Bc * Nc) / 8, 256>>>();
    k_edge<<<512, 256>>>();
    k_fin<<<1, Oc>>>(gamma, beta);
    k_out<<<dim3(Nc / 64, Bc), 256>>>(out);
}

// round 17
// speedup vs baseline: 4.3917x; 4.3917x over previous
#include <cuda_runtime.h>
#include <math.h>

// Problem constants
constexpr int Bc = 8;
constexpr int Cc = 64;
constexpr int Nc = 4096;
constexpr int Kc = 20;
constexpr int Oc = 64;
constexpr float BN_EPS = 1e-5f;
constexpr float NEG_SLOPE = 0.2f;
constexpr float FLT_BIG = 3.4e38f;

constexpr int TI = 128;      // queries per block
constexpr int TJ = 128;      // candidate tile size
constexpr int APAD = 132;    // padded row stride (floats)
constexpr int NT = 512;      // threads per block (knn)

// -------------------- device scratch (no allocations allowed) --------------------
__device__ float  g_xx[Bc * Nc];            // squared norms
__device__ int    g_idx[Bc * Nc * Kc];      // knn indices
__device__ float  g_P[Bc * Nc * Oc];        // W1 . x_j projection
__device__ float  g_Q[Bc * Nc * Oc];        // (W2-W1) . x_i projection
__device__ float  g_mx[Bc * Nc * Oc];       // max_k h
__device__ float  g_mn[Bc * Nc * Oc];       // min_k h
__device__ double g_sum[Oc];
__device__ double g_sumsq[Oc];
__device__ float  g_scale[Oc];
__device__ float  g_shift[Oc];
__device__ float  g_W1t[Cc * Oc];
__device__ float  g_Wdt[Cc * Oc];

// -------------------- f32x2 packed helpers --------------------
typedef unsigned long long u64;
typedef unsigned int u32;
__device__ __forceinline__ u64 dup2(float v) {
    u64 r; asm("mov.b64 %0, {%1, %1};" : "=l"(r) : "f"(v)); return r;
}
__device__ __forceinline__ void ffma2(u64& d, u64 a, u64 b) {
    asm("fma.rn.f32x2 %0, %1, %2, %0;" : "+l"(d) : "l"(a), "l"(b));
}
__device__ __forceinline__ u64 fma2o(u64 a, u64 b, u64 c) {
    u64 r; asm("fma.rn.f32x2 %0, %1, %2, %3;" : "=l"(r) : "l"(a), "l"(b), "l"(c));
    return r;
}
__device__ __forceinline__ u64 add2(u64 a, u64 b) {
    u64 r; asm("add.rn.f32x2 %0, %1, %2;" : "=l"(r) : "l"(a), "l"(b));
    return r;
}
__device__ __forceinline__ void unpack2(u64 v, float& lo, float& hi) {
    asm("mov.b64 {%0, %1}, %2;" : "=f"(lo), "=f"(hi) : "l"(v));
}
// orderable float mapping: monotonic uint32 key (handles negatives)
__device__ __forceinline__ u32 ordf(float f) {
    u32 u = __float_as_uint(f);
    return (u & 0x80000000u) ? ~u : (u | 0x80000000u);
}
__device__ __forceinline__ float inv_ordf(u32 v) {
    u32 u = (v & 0x80000000u) ? (v & 0x7FFFFFFFu) : ~v;
    return __uint_as_float(u);
}

constexpr u64 KEY_MAX = 0xFFFFFFFFFFFFFFFFull;

// -------------------- kernel: squared norms --------------------
__global__ void k_xx(const float* __restrict__ x) {
    int t = blockIdx.x * blockDim.x + threadIdx.x;    // over B*N
    int b = t >> 12;
    int n = t & (Nc - 1);
    const float* xb = x + (size_t)b * Cc * Nc + n;
    float s = 0.f;
#pragma unroll
    for (int c = 0; c < Cc; ++c) {
        float v = xb[c * Nc];
        s = fmaf(v, v, s);
    }
    g_xx[t] = s;
}

// -------------------- kernel: prep W transposes + zero stats --------------------
__global__ void k_prep(const float* __restrict__ W) {
    int t = blockIdx.x * blockDim.x + threadIdx.x;
    if (t < Cc * Oc) {
        int c = t & 63;
        int o = t >> 6;
        float w1 = W[o * (2 * Cc) + c];
        float w2 = W[o * (2 * Cc) + Cc + c];
        g_W1t[c * Oc + o] = w1;
        g_Wdt[c * Oc + o] = w2 - w1;
    }
    if (blockIdx.x == 0 && t < Oc) {
        g_sum[t] = 0.0;
        g_sumsq[t] = 0.0;
    }
}

// -------------------- kernel: P and Q projections --------------------
__global__ void __launch_bounds__(256) k_pq(const float* __restrict__ x) {
    int b  = blockIdx.y;
    int n0 = blockIdx.x * 32;
    int o  = threadIdx.x & 63;
    int gg = threadIdx.x >> 6;
    __shared__ float xs[Cc][36];

    for (int t = threadIdx.x; t < Cc * 32; t += 256) {
        int nn = t & 31;
        int c  = t >> 5;
        xs[c][nn] = x[(size_t)b * Cc * Nc + c * Nc + n0 + nn];
    }
    __syncthreads();

    float ap[8], aq[8];
#pragma unroll
    for (int r = 0; r < 8; ++r) { ap[r] = 0.f; aq[r] = 0.f; }
    const int nbase = gg * 8;

#pragma unroll 8
    for (int c = 0; c < Cc; ++c) {
        float w1 = __ldg(&g_W1t[c * Oc + o]);
        float wd = __ldg(&g_Wdt[c * Oc + o]);
        float4 v0 = *(const float4*)&xs[c][nbase];
        float4 v1 = *(const float4*)&xs[c][nbase + 4];
        ap[0] = fmaf(w1, v0.x, ap[0]); aq[0] = fmaf(wd, v0.x, aq[0]);
        ap[1] = fmaf(w1, v0.y, ap[1]); aq[1] = fmaf(wd, v0.y, aq[1]);
        ap[2] = fmaf(w1, v0.z, ap[2]); aq[2] = fmaf(wd, v0.z, aq[2]);
        ap[3] = fmaf(w1, v0.w, ap[3]); aq[3] = fmaf(wd, v0.w, aq[3]);
        ap[4] = fmaf(w1, v1.x, ap[4]); aq[4] = fmaf(wd, v1.x, aq[4]);
        ap[5] = fmaf(w1, v1.y, ap[5]); aq[5] = fmaf(wd, v1.y, aq[5]);
        ap[6] = fmaf(w1, v1.z, ap[6]); aq[6] = fmaf(wd, v1.z, aq[6]);
        ap[7] = fmaf(w1, v1.w, ap[7]); aq[7] = fmaf(wd, v1.w, aq[7]);
    }

    int row0 = b * Nc + n0 + nbase;
#pragma unroll
    for (int r = 0; r < 8; ++r) {
        g_P[(size_t)(row0 + r) * Oc + o] = ap[r];
        g_Q[(size_t)(row0 + r) * Oc + o] = aq[r];
    }
}

// -------------------- scan insert (rare path): build key, insertion sort --------
__device__ __forceinline__ void insert_key(
    u64* keys, int tid, float d, int jg, float& worstf)
{
    u64 key = ((u64)ordf(d) << 32) | (u32)jg;
    int p = Kc - 1;
    while (p > 0) {
        u64 v = keys[(p - 1) * NT + tid];
        if (v < key) break;
        keys[p * NT + tid] = v;
        --p;
    }
    keys[p * NT + tid] = key;
    u32 hi = (u32)(keys[(Kc - 1) * NT + tid] >> 32);
    worstf = (hi == 0xFFFFFFFFu) ? FLT_BIG : inv_ordf(hi);
}

// -------------------- kernel: GEMM-tiled KNN v10 --------------------
// R10 structure (proven 1250-class) with an instruction diet:
//  - GEMM packs accumulators along j: 4 A-dup MOVs (not 8 B-dups), B loads
//    arrive packed (3 LDS + 4 MOV + 16 FFMA2 per c-step, was 27 inst).
//  - Epilogue: packed xxj pair loads, dup2(xxi) hoisted out of tile loop.
//  - Scan: 8-wide batches with FMNMX min-tree fast path; per-element checks
//    (registers already loaded) only if the batch min qualifies.
// Distance values and insert order are bit-identical to R10.
__global__ void __launch_bounds__(NT) k_knn10(const float* __restrict__ x) {
    extern __shared__ float sm[];
    u64*   keys = (u64*)sm;                        // [Kc][NT]
    float* As   = sm + (Kc * NT * 2);              // [Cc][APAD]
    float* Bs   = As + Cc * APAD;                  // [Cc][APAD]
    float* Ds   = Bs + Cc * APAD;                  // [TJ][APAD]
    float* sxxi = Ds + TJ * APAD;                  // [128]
    float* sxxj = sxxi + 128;                      // [128]

    const int tid = threadIdx.x;
    const int b   = blockIdx.y;
    const int i0  = blockIdx.x * TI;
    const float* xb = x + (size_t)b * Cc * Nc;

    const int ti = tid & 31;      // i-group (4 queries)
    const int tj = tid >> 5;      // j-group (8 candidates), warp-uniform
    const int qi = tid & 127;     // scan query
    const int qq = tid >> 7;      // scan quarter

    // load A tile: As[c][ii] = x[b][c][i0+ii]
    {
        int col = (tid & 31) * 4;
        int cb  = tid >> 5;
#pragma unroll
        for (int cc = 0; cc < 4; ++cc) {
            int c = cb + cc * 16;
            float4 v = *(const float4*)&xb[(size_t)c * Nc + i0 + col];
            *(float4*)&As[c * APAD + col] = v;
        }
    }
    if (tid < 128) sxxi[tid] = g_xx[b * Nc + i0 + tid];
#pragma unroll
    for (int kk = 0; kk < Kc; ++kk) keys[kk * NT + tid] = KEY_MAX;
    __syncthreads();

    // hoisted: duplicated query norms for this thread's 4 i's
    u64 xid[4];
    {
        float4 xi4 = *(const float4*)&sxxi[ti * 4];
        xid[0] = dup2(xi4.x); xid[1] = dup2(xi4.y);
        xid[2] = dup2(xi4.z); xid[3] = dup2(xi4.w);
    }
    const u64 neg2 = dup2(-2.f);
    float worstf = FLT_BIG;

    for (int t = 0; t < Nc / TJ; ++t) {
        const int j0 = t * TJ;

        // load B tile global -> shared (overlaps with scan below)
        {
            int col = (tid & 31) * 4;
            int cb  = tid >> 5;
#pragma unroll
            for (int cc = 0; cc < 4; ++cc) {
                int c = cb + cc * 16;
                float4 v = *(const float4*)&xb[(size_t)c * Nc + j0 + col];
                *(float4*)&Bs[c * APAD + col] = v;
            }
        }
        if (tid < 128) sxxj[tid] = g_xx[b * Nc + j0 + tid];

        // scan previous tile's distances (min-tree fast path)
        if (t > 0) {
            const int jp0 = j0 - TJ + qq * 32;
            const float* drow = &Ds[qq * 32 * APAD + qi];
#pragma unroll
            for (int jb = 0; jb < 32; jb += 8) {
                float d[8];
#pragma unroll
                for (int u = 0; u < 8; ++u) d[u] = drow[(jb + u) * APAD];
                float m01 = fminf(d[0], d[1]), m23 = fminf(d[2], d[3]);
                float m45 = fminf(d[4], d[5]), m67 = fminf(d[6], d[7]);
                float m = fminf(fminf(m01, m23), fminf(m45, m67));
                if (m < worstf) {
#pragma unroll
                    for (int u = 0; u < 8; ++u) {
                        if (d[u] < worstf)
                            insert_key(keys, tid, d[u], jp0 + jb + u, worstf);
                    }
                }
            }
        }
        __syncthreads();   // B ready; Ds free for rewrite

        // ---- 4i x 8j GEMM, accumulators packed along j ----
        u64 acc[4][4];   // [i][j-pair]
#pragma unroll
        for (int i = 0; i < 4; ++i)
#pragma unroll
            for (int jp = 0; jp < 4; ++jp) acc[i][jp] = 0ULL;

#pragma unroll 4
        for (int c = 0; c < Cc; ++c) {
            float4 av = *(const float4*)&As[c * APAD + ti * 4];
            u64 a0 = dup2(av.x), a1 = dup2(av.y), a2 = dup2(av.z), a3 = dup2(av.w);
            ulonglong2 b01 = *(const ulonglong2*)&Bs[c * APAD + tj * 8];
            ulonglong2 b23 = *(const ulonglong2*)&Bs[c * APAD + tj * 8 + 4];
            ffma2(acc[0][0], a0, b01.x); ffma2(acc[1][0], a1, b01.x);
            ffma2(acc[2][0], a2, b01.x); ffma2(acc[3][0], a3, b01.x);
            ffma2(acc[0][1], a0, b01.y); ffma2(acc[1][1], a1, b01.y);
            ffma2(acc[2][1], a2, b01.y); ffma2(acc[3][1], a3, b01.y);
            ffma2(acc[0][2], a0, b23.x); ffma2(acc[1][2], a1, b23.x);
            ffma2(acc[2][2], a2, b23.x); ffma2(acc[3][2], a3, b23.x);
            ffma2(acc[0][3], a0, b23.y); ffma2(acc[1][3], a1, b23.y);
            ffma2(acc[2][3], a2, b23.y); ffma2(acc[3][3], a3, b23.y);
        }

        // epilogue: d = xxi + xxj - 2*inner (j-packed), store Ds[j][i]
        {
            ulonglong2 xj01 = *(const ulonglong2*)&sxxj[tj * 8];
            ulonglong2 xj23 = *(const ulonglong2*)&sxxj[tj * 8 + 4];
            u64 xjp[4] = {xj01.x, xj01.y, xj23.x, xj23.y};
#pragma unroll
            for (int jp = 0; jp < 4; ++jp) {
                int r0 = (tj * 8 + jp * 2) * APAD + ti * 4;
                int r1 = r0 + APAD;
#pragma unroll
                for (int i = 0; i < 4; ++i) {
                    u64 d2 = fma2o(acc[i][jp], neg2, add2(xid[i], xjp[jp]));
                    float lo, hi;
                    unpack2(d2, lo, hi);
                    Ds[r0 + i] = lo;
                    Ds[r1 + i] = hi;
                }
            }
        }
        __syncthreads();   // Ds visible; Bs consumed
    }

    // scan last tile (min-tree fast path)
    {
        const int jp0 = Nc - TJ + qq * 32;
        const float* drow = &Ds[qq * 32 * APAD + qi];
#pragma unroll
        for (int jb = 0; jb < 32; jb += 8) {
            float d[8];
#pragma unroll
            for (int u = 0; u < 8; ++u) d[u] = drow[(jb + u) * APAD];
            float m01 = fminf(d[0], d[1]), m23 = fminf(d[2], d[3]);
            float m45 = fminf(d[4], d[5]), m67 = fminf(d[6], d[7]);
            float m = fminf(fminf(m01, m23), fminf(m45, m67));
            if (m < worstf) {
#pragma unroll
                for (int u = 0; u < 8; ++u) {
                    if (d[u] < worstf)
                        insert_key(keys, tid, d[u], jp0 + jb + u, worstf);
                }
            }
        }
    }
    __syncthreads();

    // merge the 4 quarter lists per query (u64 order = dist, then idx)
    if (tid < 128) {
        u64 tk[Kc];
#pragma unroll
        for (int kk = 0; kk < Kc; ++kk) tk[kk] = KEY_MAX;
        for (int s = 0; s < 4; ++s) {
#pragma unroll 1
            for (int kk = 0; kk < Kc; ++kk) {
                u64 key = keys[kk * NT + s * 128 + tid];
                if (!(key < tk[Kc - 1])) break;   // source sorted ascending
                int p = Kc - 1;
                while (p > 0 && tk[p - 1] > key) {
                    tk[p] = tk[p - 1];
                    --p;
                }
                tk[p] = key;
            }
        }
        int* op = &g_idx[((size_t)(b * Nc + i0 + tid)) * Kc];
#pragma unroll
        for (int kk = 0; kk < Kc; ++kk) op[kk] = (int)(u32)(tk[kk] & 0xFFFFFFFFull);
    }
}

// -------------------- kernel: gather + max/min + BN stats --------------------
__global__ void __launch_bounds__(256) k_edge() {
    int o  = threadIdx.x & 63;
    int gg = threadIdx.x >> 6;
    float s1 = 0.f, s2v = 0.f;

    for (int row = blockIdx.x * 4 + gg; row < Bc * Nc; row += gridDim.x * 4) {
        int b  = row >> 12;
        int nb = b << 12;
        float qv = g_Q[(size_t)row * Oc + o];
        const int* ip = &g_idx[(size_t)row * Kc];
        float mx = -FLT_BIG, mn = FLT_BIG;
#pragma unroll
        for (int kk = 0; kk < Kc; ++kk) {
            int j = __ldg(&ip[kk]);
            float h = g_P[(size_t)(nb + j) * Oc + o] + qv;
            mx = fmaxf(mx, h);
            mn = fminf(mn, h);
            s1 += h;
            s2v = fmaf(h, h, s2v);
        }
        g_mx[(size_t)row * Oc + o] = mx;
        g_mn[(size_t)row * Oc + o] = mn;
    }

    __shared__ float sa[4][64], sb[4][64];
    sa[gg][o] = s1;
    sb[gg][o] = s2v;
    __syncthreads();
    if (gg == 0) {
        float t1 = sa[0][o] + sa[1][o] + sa[2][o] + sa[3][o];
        float t2 = sb[0][o] + sb[1][o] + sb[2][o] + sb[3][o];
        atomicAdd(&g_sum[o], (double)t1);
        atomicAdd(&g_sumsq[o], (double)t2);
    }
}

// -------------------- kernel: finalize BN affine --------------------
__global__ void k_fin(const float* __restrict__ gamma, const float* __restrict__ beta) {
    int o = threadIdx.x;
    const double cnt = (double)Bc * Nc * Kc;
    double mean = g_sum[o] / cnt;
    double var  = g_sumsq[o] / cnt - mean * mean;
    float a = gamma[o] * rsqrtf((float)var + BN_EPS);
    g_scale[o] = a;
    g_shift[o] = beta[o] - (float)mean * a;
}

// -------------------- kernel: apply affine + leaky + transpose to [B,O,N] --------------------
__global__ void __launch_bounds__(256) k_out(float* __restrict__ out) {
    int b  = blockIdx.y;
    int n0 = blockIdx.x * 64;
    __shared__ float sh[64][65];

    for (int t = threadIdx.x; t < 4096; t += 256) {
        int o  = t & 63;
        int nn = t >> 6;
        int row = b * Nc + n0 + nn;
        float a = g_scale[o];
        float m = (a >= 0.f) ? g_mx[(size_t)row * Oc + o] : g_mn[(size_t)row * Oc + o];
        float v = fmaf(a, m, g_shift[o]);
        v = (v >= 0.f) ? v : NEG_SLOPE * v;
        sh[o][nn] = v;
    }
    __syncthreads();
    for (int t = threadIdx.x; t < 4096; t += 256) {
        int nn = t & 63;
        int o  = t >> 6;
        out[((size_t)(b * Oc + o)) * Nc + n0 + nn] = sh[o][nn];
    }
}

// -------------------- launch --------------------
extern "C" void kernel_launch(void* const* d_in, const int* in_sizes, int n_in,
                              void* d_out, int out_size) {
    const float* x     = (const float*)d_in[0];   // [B, C, N]
    const float* W     = (const float*)d_in[1];   // [O, 2C]
    const float* gamma = (const float*)d_in[2];   // [O]
    const float* beta  = (const float*)d_in[3];   // [O]
    float* out = (float*)d_out;                   // [B, O, N]

    // keys [Kc][NT] u64 + As/Bs [Cc][APAD] + Ds [TJ][APAD] + sxx
    constexpr size_t KNN_SMEM =
        (size_t)Kc * NT * 8 +
        (size_t)(2 * Cc * APAD + TJ * APAD + 256) * 4;

    static bool attr_set = false;
    if (!attr_set) {
        cudaFuncSetAttribute(k_knn10, cudaFuncAttributeMaxDynamicSharedMemorySize,
                             (int)KNN_SMEM);
        attr_set = true;
    }

    k_xx<<<(Bc * Nc) / 256, 256>>>(x);
    k_prep<<<16, 256>>>(W);
    k_pq<<<dim3(Nc / 32, Bc), 256>>>(x);
    k_knn10<<<dim3(Nc / TI, Bc), NT, KNN_SMEM>>>(x);
    k_edge<<<512, 256>>>();
    k_fin<<<1, Oc>>>(gamma, beta);
    k_out<<<dim3(Nc / 64, Bc), 256>>>(out);
}